// round 1
// baseline (speedup 1.0000x reference)
#include <cuda_runtime.h>
#include <math.h>
#include <stdint.h>

// Problem constants
#define BB   4
#define LL   1024
#define BL   4096          // B*L
#define DD   768
#define HH   12
#define DKH  64
#define FF   3072
#define MDIST 100
#define TBL  201

// ---------------- scratch (device globals: allocation-free rule) -------------
__device__ float g_Q[BL * DD];
__device__ float g_K[BL * DD];
__device__ float g_V[BL * DD];
__device__ float g_S[(size_t)BB * HH * LL * LL];   // scores / attn (201 MB)
__device__ float g_ctx[BL * DD];
__device__ float g_pre[BL * DD];                   // pre-LN buffer (reused)
__device__ float g_t1[BL * DD];                    // after LN1
__device__ float g_ff[BL * FF];

// ---------------- generic 64x64-tile fp32 GEMM, C = A[M,K] @ B[K,N] ----------
// EPI: 0 = +bias ; 1 = +bias,relu ; 2 = +bias,+residual
template<int EPI>
__global__ void __launch_bounds__(256)
gemm64(const float* __restrict__ A, const float* __restrict__ Bm,
       const float* __restrict__ bias, const float* __restrict__ res,
       float* __restrict__ C, int K, int N)
{
    __shared__ float As[32][64];   // [k][m] (A transposed in smem)
    __shared__ float Bs[32][64];   // [k][n]
    const int m0 = blockIdx.y * 64;
    const int n0 = blockIdx.x * 64;
    const int tid = threadIdx.x;
    const int ty = tid >> 4, tx = tid & 15;

    float acc[4][4] = {};

    for (int k0 = 0; k0 < K; k0 += 32) {
        #pragma unroll
        for (int it = 0; it < 2; ++it) {
            int li = tid + it * 256;
            int r = li >> 3, c4 = li & 7;                 // A tile: 64 rows x 8 float4
            float4 a4 = *(const float4*)(A + (size_t)(m0 + r) * K + k0 + c4 * 4);
            As[c4 * 4 + 0][r] = a4.x;
            As[c4 * 4 + 1][r] = a4.y;
            As[c4 * 4 + 2][r] = a4.z;
            As[c4 * 4 + 3][r] = a4.w;
            int rb = li >> 4, cb = li & 15;               // B tile: 32 rows x 16 float4
            float4 b4 = *(const float4*)(Bm + (size_t)(k0 + rb) * N + n0 + cb * 4);
            *(float4*)&Bs[rb][cb * 4] = b4;
        }
        __syncthreads();
        #pragma unroll
        for (int kk = 0; kk < 32; ++kk) {
            float4 av = *(float4*)&As[kk][ty * 4];
            float4 bv = *(float4*)&Bs[kk][tx * 4];
            float a_[4] = {av.x, av.y, av.z, av.w};
            float b_[4] = {bv.x, bv.y, bv.z, bv.w};
            #pragma unroll
            for (int i = 0; i < 4; ++i)
                #pragma unroll
                for (int j = 0; j < 4; ++j)
                    acc[i][j] = fmaf(a_[i], b_[j], acc[i][j]);
        }
        __syncthreads();
    }

    #pragma unroll
    for (int i = 0; i < 4; ++i) {
        int row = m0 + ty * 4 + i;
        #pragma unroll
        for (int j = 0; j < 4; ++j) {
            int col = n0 + tx * 4 + j;
            float v = acc[i][j] + bias[col];
            if (EPI == 1) v = fmaxf(v, 0.0f);
            if (EPI == 2) v += res[(size_t)row * N + col];
            C[(size_t)row * N + col] = v;
        }
    }
}

// ------------- scores: S = QK^T/8 + relpos bias, masked ----------------------
__global__ void __launch_bounds__(256)
scores_kernel(const float* __restrict__ Q, const float* __restrict__ Kb,
              const float* __restrict__ pos, const float* __restrict__ pmask,
              const float* __restrict__ amask, const unsigned char* __restrict__ pad,
              const float* __restrict__ table, float* __restrict__ S)
{
    __shared__ float Qs[64][65];
    __shared__ float Ks[64][65];
    __shared__ float pxq[64], pyq[64], pmq[64];
    __shared__ float pxk[64], pyk[64], pmk[64];

    const int k0 = blockIdx.x * 64;
    const int q0 = blockIdx.y * 64;
    const int bh = blockIdx.z;
    const int b = bh / HH, h = bh % HH;
    const int tid = threadIdx.x;

    #pragma unroll
    for (int it = 0; it < 4; ++it) {
        int li = tid + it * 256;
        int r = li >> 4, c4 = li & 15;
        float4 q4 = *(const float4*)(Q + ((size_t)(b * LL + q0 + r)) * DD + h * DKH + c4 * 4);
        Qs[r][c4 * 4 + 0] = q4.x; Qs[r][c4 * 4 + 1] = q4.y;
        Qs[r][c4 * 4 + 2] = q4.z; Qs[r][c4 * 4 + 3] = q4.w;
        float4 k4 = *(const float4*)(Kb + ((size_t)(b * LL + k0 + r)) * DD + h * DKH + c4 * 4);
        Ks[r][c4 * 4 + 0] = k4.x; Ks[r][c4 * 4 + 1] = k4.y;
        Ks[r][c4 * 4 + 2] = k4.z; Ks[r][c4 * 4 + 3] = k4.w;
    }
    if (tid < 64) {
        int l = b * LL + q0 + tid;
        pxq[tid] = pos[(size_t)l * 2 + 0];
        pyq[tid] = pos[(size_t)l * 2 + 1];
        pmq[tid] = pmask[l];
    } else if (tid < 128) {
        int t = tid - 64;
        int l = b * LL + k0 + t;
        pxk[t] = pos[(size_t)l * 2 + 0];
        pyk[t] = pos[(size_t)l * 2 + 1];
        pmk[t] = pmask[l];
    }
    __syncthreads();

    const int ty = tid >> 4, tx = tid & 15;
    float acc[4][4] = {};
    #pragma unroll 8
    for (int d = 0; d < DKH; ++d) {
        float a_[4], b_[4];
        #pragma unroll
        for (int i = 0; i < 4; ++i) a_[i] = Qs[ty * 4 + i][d];
        #pragma unroll
        for (int j = 0; j < 4; ++j) b_[j] = Ks[tx * 4 + j][d];
        #pragma unroll
        for (int i = 0; i < 4; ++i)
            #pragma unroll
            for (int j = 0; j < 4; ++j)
                acc[i][j] = fmaf(a_[i], b_[j], acc[i][j]);
    }

    #pragma unroll
    for (int i = 0; i < 4; ++i) {
        int qi = ty * 4 + i;
        int qg = q0 + qi;
        #pragma unroll
        for (int j = 0; j < 4; ++j) {
            int kj = tx * 4 + j;
            int kg = k0 + kj;
            float s = acc[i][j] * 0.125f;   // 1/sqrt(64)
            float ddx = rintf(pxq[qi] - pxk[kj]);
            float ddy = rintf(pyq[qi] - pyk[kj]);
            ddx = fminf(fmaxf(ddx, -(float)MDIST), (float)MDIST);
            ddy = fminf(fmaxf(ddy, -(float)MDIST), (float)MDIST);
            int dx = (int)ddx + MDIST;
            int dy = (int)ddy + MDIST;
            float bias = table[((size_t)h * TBL + dy) * TBL + dx] * (pmq[qi] * pmk[kj]);
            s += bias;
            bool inval = (amask[((size_t)(b * LL + qg)) * LL + kg] == 0.0f) ||
                         (pad[b * LL + kg] != 0);
            S[((size_t)bh << 20) + (size_t)qg * LL + kg] = inval ? -1e9f : s;
        }
    }
}

// ------------- softmax over k (row = 1024), in place -------------------------
__global__ void __launch_bounds__(256)
softmax_kernel(float* __restrict__ S)
{
    const size_t row = blockIdx.x;
    float4* p = (float4*)(S + row * LL);
    const int tid = threadIdx.x;
    float4 v = p[tid];

    __shared__ float red[256];
    float m = fmaxf(fmaxf(v.x, v.y), fmaxf(v.z, v.w));
    red[tid] = m; __syncthreads();
    for (int s = 128; s > 0; s >>= 1) {
        if (tid < s) red[tid] = fmaxf(red[tid], red[tid + s]);
        __syncthreads();
    }
    m = red[0];
    __syncthreads();

    v.x = expf(v.x - m); v.y = expf(v.y - m);
    v.z = expf(v.z - m); v.w = expf(v.w - m);
    float sm = v.x + v.y + v.z + v.w;
    red[tid] = sm; __syncthreads();
    for (int s = 128; s > 0; s >>= 1) {
        if (tid < s) red[tid] += red[tid + s];
        __syncthreads();
    }
    float inv = 1.0f / red[0];
    v.x *= inv; v.y *= inv; v.z *= inv; v.w *= inv;
    p[tid] = v;
}

// ------------- PV: ctx = attn @ V --------------------------------------------
__global__ void __launch_bounds__(256)
pv_kernel(const float* __restrict__ S, const float* __restrict__ V,
          float* __restrict__ C)
{
    __shared__ float As[64][65];  // attn [q][k]
    __shared__ float Vs[64][64];  // V    [k][d]
    const int q0 = blockIdx.x * 64;
    const int bh = blockIdx.y;
    const int b = bh / HH, h = bh % HH;
    const int tid = threadIdx.x;
    const int ty = tid >> 4, tx = tid & 15;

    const float* Sb = S + ((size_t)bh << 20);
    float acc[4][4] = {};

    for (int kc = 0; kc < LL; kc += 64) {
        #pragma unroll
        for (int it = 0; it < 4; ++it) {
            int li = tid + it * 256;
            int r = li >> 4, c4 = li & 15;
            float4 a4 = *(const float4*)(Sb + (size_t)(q0 + r) * LL + kc + c4 * 4);
            As[r][c4 * 4 + 0] = a4.x; As[r][c4 * 4 + 1] = a4.y;
            As[r][c4 * 4 + 2] = a4.z; As[r][c4 * 4 + 3] = a4.w;
            float4 v4 = *(const float4*)(V + (size_t)(b * LL + kc + r) * DD + h * DKH + c4 * 4);
            *(float4*)&Vs[r][c4 * 4] = v4;
        }
        __syncthreads();
        #pragma unroll 8
        for (int kk = 0; kk < 64; ++kk) {
            float a_[4];
            #pragma unroll
            for (int i = 0; i < 4; ++i) a_[i] = As[ty * 4 + i][kk];
            float4 bv = *(float4*)&Vs[kk][tx * 4];
            float b_[4] = {bv.x, bv.y, bv.z, bv.w};
            #pragma unroll
            for (int i = 0; i < 4; ++i)
                #pragma unroll
                for (int j = 0; j < 4; ++j)
                    acc[i][j] = fmaf(a_[i], b_[j], acc[i][j]);
        }
        __syncthreads();
    }

    #pragma unroll
    for (int i = 0; i < 4; ++i) {
        int row = b * LL + q0 + ty * 4 + i;
        #pragma unroll
        for (int j = 0; j < 4; ++j) {
            C[(size_t)row * DD + h * DKH + tx * 4 + j] = acc[i][j];
        }
    }
}

// ------------- LayerNorm over last dim (768) ----------------------------------
__global__ void __launch_bounds__(256)
ln_kernel(const float* __restrict__ X, const float* __restrict__ g,
          const float* __restrict__ bt, float* __restrict__ O)
{
    const int row = blockIdx.x;
    const float* x = X + (size_t)row * DD;
    const int tid = threadIdx.x;

    float v[3];
    #pragma unroll
    for (int i = 0; i < 3; ++i) v[i] = x[tid + i * 256];

    __shared__ float red[256];
    float s = v[0] + v[1] + v[2];
    red[tid] = s; __syncthreads();
    for (int st = 128; st > 0; st >>= 1) {
        if (tid < st) red[tid] += red[tid + st];
        __syncthreads();
    }
    float mean = red[0] * (1.0f / DD);
    __syncthreads();

    float d0 = v[0] - mean, d1 = v[1] - mean, d2 = v[2] - mean;
    red[tid] = d0 * d0 + d1 * d1 + d2 * d2; __syncthreads();
    for (int st = 128; st > 0; st >>= 1) {
        if (tid < st) red[tid] += red[tid + st];
        __syncthreads();
    }
    float var = red[0] * (1.0f / DD);
    float inv = rsqrtf(var + 1e-5f);

    float* o = O + (size_t)row * DD;
    #pragma unroll
    for (int i = 0; i < 3; ++i) {
        int c = tid + i * 256;
        o[c] = (v[i] - mean) * inv * g[c] + bt[c];
    }
}

// ------------------------------- launch ---------------------------------------
extern "C" void kernel_launch(void* const* d_in, const int* in_sizes, int n_in,
                              void* d_out, int out_size)
{
    const float* tokens = (const float*)d_in[0];
    const float* pos    = (const float*)d_in[1];
    const float* pmask  = (const float*)d_in[2];
    const float* amask  = (const float*)d_in[3];
    const unsigned char* pad = (const unsigned char*)d_in[4];
    const float* Wq = (const float*)d_in[5];
    const float* bq = (const float*)d_in[6];
    const float* Wk = (const float*)d_in[7];
    const float* bk = (const float*)d_in[8];
    const float* Wv = (const float*)d_in[9];
    const float* bv = (const float*)d_in[10];
    const float* Wo = (const float*)d_in[11];
    const float* bo = (const float*)d_in[12];
    const float* table = (const float*)d_in[13];
    const float* W1 = (const float*)d_in[14];
    const float* b1 = (const float*)d_in[15];
    const float* W2 = (const float*)d_in[16];
    const float* b2 = (const float*)d_in[17];
    const float* ln1g = (const float*)d_in[18];
    const float* ln1b = (const float*)d_in[19];
    const float* ln2g = (const float*)d_in[20];
    const float* ln2b = (const float*)d_in[21];
    float* out = (float*)d_out;

    float *Qb, *Kb, *Vb, *Sb, *Cb, *Pb, *Tb, *Fb;
    cudaGetSymbolAddress((void**)&Qb, g_Q);
    cudaGetSymbolAddress((void**)&Kb, g_K);
    cudaGetSymbolAddress((void**)&Vb, g_V);
    cudaGetSymbolAddress((void**)&Sb, g_S);
    cudaGetSymbolAddress((void**)&Cb, g_ctx);
    cudaGetSymbolAddress((void**)&Pb, g_pre);
    cudaGetSymbolAddress((void**)&Tb, g_t1);
    cudaGetSymbolAddress((void**)&Fb, g_ff);

    dim3 gD(DD / 64, BL / 64);     // 12 x 64
    dim3 gF(FF / 64, BL / 64);     // 48 x 64

    // QKV projections
    gemm64<0><<<gD, 256>>>(tokens, Wq, bq, nullptr, Qb, DD, DD);
    gemm64<0><<<gD, 256>>>(tokens, Wk, bk, nullptr, Kb, DD, DD);
    gemm64<0><<<gD, 256>>>(tokens, Wv, bv, nullptr, Vb, DD, DD);

    // scores + relpos bias + masks
    dim3 gs(LL / 64, LL / 64, BB * HH);   // 16 x 16 x 48
    scores_kernel<<<gs, 256>>>(Qb, Kb, pos, pmask, amask, pad, table, Sb);

    // softmax
    softmax_kernel<<<BB * HH * LL, 256>>>(Sb);

    // attn @ V
    dim3 gp(LL / 64, BB * HH);            // 16 x 48
    pv_kernel<<<gp, 256>>>(Sb, Vb, Cb);

    // output projection + residual, LN1
    gemm64<2><<<gD, 256>>>(Cb, Wo, bo, tokens, Pb, DD, DD);
    ln_kernel<<<BL, 256>>>(Pb, ln1g, ln1b, Tb);

    // FFN
    gemm64<1><<<gF, 256>>>(Tb, W1, b1, nullptr, Fb, DD, FF);
    gemm64<2><<<gD, 256>>>(Fb, W2, b2, Tb, Pb, FF, DD);
    ln_kernel<<<BL, 256>>>(Pb, ln2g, ln2b, out);
}

// round 2
// speedup vs baseline: 1.0777x; 1.0777x over previous
#include <cuda_runtime.h>
#include <math.h>
#include <stdint.h>

#define BB   4
#define LL   1024
#define BL   4096
#define DD   768
#define HH   12
#define DKH  64
#define FF   3072
#define MDIST 100
#define TBL  201

// ---------------- scratch ----------------
__device__ float g_Q[BL * DD];
__device__ float g_K[BL * DD];
__device__ float g_V[BL * DD];
__device__ float g_S[(size_t)BB * HH * LL * LL];
__device__ float g_ctx[BL * DD];
__device__ float g_pre[BL * DD];
__device__ float g_t1[BL * DD];
__device__ float g_ff[BL * FF];

// ---------- 128x128x16 fp32 GEMM, double-buffered, 8x8 micro ----------
// EPI: 0 = +bias ; 1 = +bias,relu ; 2 = +bias,+residual
template<int EPI>
__global__ void __launch_bounds__(256, 2)
gemm128(const float* __restrict__ A, const float* __restrict__ Bm,
        const float* __restrict__ bias, const float* __restrict__ res,
        float* __restrict__ C, int K, int N)
{
    __shared__ float As[2][16][132];   // [k][m], stride 132: aligned LDS.128, 2-way STS
    __shared__ float Bs[2][16][128];   // [k][n]
    const int m0 = blockIdx.y * 128, n0 = blockIdx.x * 128;
    const int tid = threadIdx.x;
    const int ty = tid >> 4, tx = tid & 15;

    const int ar0 = tid >> 2;             // A rows (m) 0..63, +64 for it=1
    const int ac  = (tid & 3) * 4;        // A k-offset within tile
    const int br0 = tid >> 5;             // B rows (k) 0..7, +8 for it=1
    const int bc  = (tid & 31) * 4;       // B n-offset

    const float* Aptr = A + (size_t)(m0) * K + ac;
    const float* Bptr = Bm + n0 + bc;

    float acc[8][8] = {};

    // stage 0
    #pragma unroll
    for (int it = 0; it < 2; ++it) {
        int r = ar0 + it * 64;
        float4 a4 = *(const float4*)(Aptr + (size_t)r * K);
        As[0][ac + 0][r] = a4.x; As[0][ac + 1][r] = a4.y;
        As[0][ac + 2][r] = a4.z; As[0][ac + 3][r] = a4.w;
        int rb = br0 + it * 8;
        *(float4*)&Bs[0][rb][bc] = *(const float4*)(Bptr + (size_t)rb * N);
    }
    __syncthreads();

    const int ns = K >> 4;
    for (int s = 0; s < ns; ++s) {
        const int buf = s & 1;
        float4 pa[2], pb[2];
        if (s + 1 < ns) {
            const int k0 = (s + 1) << 4;
            #pragma unroll
            for (int it = 0; it < 2; ++it) {
                pa[it] = *(const float4*)(Aptr + (size_t)(ar0 + it * 64) * K + k0);
                pb[it] = *(const float4*)(Bptr + (size_t)(k0 + br0 + it * 8) * N);
            }
        }
        #pragma unroll
        for (int kk = 0; kk < 16; ++kk) {
            float4 a0 = *(float4*)&As[buf][kk][ty * 8];
            float4 a1 = *(float4*)&As[buf][kk][ty * 8 + 4];
            float4 b0 = *(float4*)&Bs[buf][kk][tx * 8];
            float4 b1 = *(float4*)&Bs[buf][kk][tx * 8 + 4];
            float a_[8] = {a0.x,a0.y,a0.z,a0.w,a1.x,a1.y,a1.z,a1.w};
            float b_[8] = {b0.x,b0.y,b0.z,b0.w,b1.x,b1.y,b1.z,b1.w};
            #pragma unroll
            for (int i = 0; i < 8; ++i)
                #pragma unroll
                for (int j = 0; j < 8; ++j)
                    acc[i][j] = fmaf(a_[i], b_[j], acc[i][j]);
        }
        if (s + 1 < ns) {
            #pragma unroll
            for (int it = 0; it < 2; ++it) {
                int r = ar0 + it * 64;
                As[buf ^ 1][ac + 0][r] = pa[it].x; As[buf ^ 1][ac + 1][r] = pa[it].y;
                As[buf ^ 1][ac + 2][r] = pa[it].z; As[buf ^ 1][ac + 3][r] = pa[it].w;
                *(float4*)&Bs[buf ^ 1][br0 + it * 8][bc] = pb[it];
            }
        }
        __syncthreads();
    }

    float bv[8];
    #pragma unroll
    for (int j = 0; j < 8; ++j) bv[j] = bias[n0 + tx * 8 + j];
    #pragma unroll
    for (int i = 0; i < 8; ++i) {
        size_t row = (size_t)(m0 + ty * 8 + i);
        float* cp = C + row * N + n0 + tx * 8;
        float o[8];
        #pragma unroll
        for (int j = 0; j < 8; ++j) {
            float v = acc[i][j] + bv[j];
            if (EPI == 1) v = fmaxf(v, 0.0f);
            if (EPI == 2) v += res[row * N + n0 + tx * 8 + j];
            o[j] = v;
        }
        *(float4*)cp       = *(float4*)&o[0];
        *(float4*)(cp + 4) = *(float4*)&o[4];
    }
}

// ------------- scores: S = QK^T/8 + relpos bias, masked ----------------------
__global__ void __launch_bounds__(256)
scores_kernel(const float* __restrict__ Q, const float* __restrict__ Kb,
              const float* __restrict__ pos, const float* __restrict__ pmask,
              const float* __restrict__ amask, const unsigned char* __restrict__ pad,
              const float* __restrict__ table, float* __restrict__ S)
{
    __shared__ float Qs[64][68];
    __shared__ float Ks[64][68];
    __shared__ float pxq[64], pyq[64], pmq[64];
    __shared__ float pxk[64], pyk[64], pmk[64];

    const int k0 = blockIdx.x * 64;
    const int q0 = blockIdx.y * 64;
    const int bh = blockIdx.z;
    const int b = bh / HH, h = bh % HH;
    const int tid = threadIdx.x;
    const int lr = tid >> 4, lc = (tid & 15) * 4;

    #pragma unroll
    for (int it = 0; it < 4; ++it) {
        int r = lr + it * 16;
        *(float4*)&Qs[r][lc] = *(const float4*)(Q + (size_t)(b * LL + q0 + r) * DD + h * DKH + lc);
        *(float4*)&Ks[r][lc] = *(const float4*)(Kb + (size_t)(b * LL + k0 + r) * DD + h * DKH + lc);
    }
    if (tid < 64) {
        int l = b * LL + q0 + tid;
        pxq[tid] = pos[(size_t)l * 2 + 0];
        pyq[tid] = pos[(size_t)l * 2 + 1];
        pmq[tid] = pmask[l];
    } else if (tid < 128) {
        int t = tid - 64;
        int l = b * LL + k0 + t;
        pxk[t] = pos[(size_t)l * 2 + 0];
        pyk[t] = pos[(size_t)l * 2 + 1];
        pmk[t] = pmask[l];
    }
    __syncthreads();

    const int ty = tid >> 4, tx = tid & 15;
    float acc[4][4] = {};
    #pragma unroll
    for (int d0 = 0; d0 < DKH; d0 += 4) {
        float aq[4][4], bk[4][4];
        #pragma unroll
        for (int i = 0; i < 4; ++i) *(float4*)aq[i] = *(float4*)&Qs[ty * 4 + i][d0];
        #pragma unroll
        for (int j = 0; j < 4; ++j) *(float4*)bk[j] = *(float4*)&Ks[tx * 4 + j][d0];
        #pragma unroll
        for (int u = 0; u < 4; ++u)
            #pragma unroll
            for (int i = 0; i < 4; ++i)
                #pragma unroll
                for (int j = 0; j < 4; ++j)
                    acc[i][j] = fmaf(aq[i][u], bk[j][u], acc[i][j]);
    }

    #pragma unroll
    for (int i = 0; i < 4; ++i) {
        int qi = ty * 4 + i;
        int qg = q0 + qi;
        float4 am = *(const float4*)(amask + (size_t)(b * LL + qg) * LL + k0 + tx * 4);
        float amv[4] = {am.x, am.y, am.z, am.w};
        float o[4];
        #pragma unroll
        for (int j = 0; j < 4; ++j) {
            int kj = tx * 4 + j;
            int kg = k0 + kj;
            float s = acc[i][j] * 0.125f;
            float ddx = rintf(pxq[qi] - pxk[kj]);
            float ddy = rintf(pyq[qi] - pyk[kj]);
            ddx = fminf(fmaxf(ddx, -(float)MDIST), (float)MDIST);
            ddy = fminf(fmaxf(ddy, -(float)MDIST), (float)MDIST);
            int dx = (int)ddx + MDIST;
            int dy = (int)ddy + MDIST;
            float bias = table[((size_t)h * TBL + dy) * TBL + dx] * (pmq[qi] * pmk[kj]);
            s += bias;
            bool inval = (amv[j] == 0.0f) || (pad[b * LL + kg] != 0);
            o[j] = inval ? -1e9f : s;
        }
        *(float4*)(S + ((size_t)bh << 20) + (size_t)qg * LL + k0 + tx * 4) = *(float4*)o;
    }
}

// ------------- softmax: warp per row ------------------------------------------
__global__ void __launch_bounds__(256)
softmax_kernel(float* __restrict__ S)
{
    const int w = threadIdx.x >> 5, lane = threadIdx.x & 31;
    const size_t row = (size_t)blockIdx.x * 8 + w;
    float4* p = (float4*)(S + row * LL);
    float4 v[8];
    #pragma unroll
    for (int j = 0; j < 8; ++j) v[j] = p[lane + 32 * j];

    float m = -1e30f;
    #pragma unroll
    for (int j = 0; j < 8; ++j)
        m = fmaxf(m, fmaxf(fmaxf(v[j].x, v[j].y), fmaxf(v[j].z, v[j].w)));
    #pragma unroll
    for (int o = 16; o > 0; o >>= 1) m = fmaxf(m, __shfl_xor_sync(0xffffffffu, m, o));

    float sum = 0.0f;
    #pragma unroll
    for (int j = 0; j < 8; ++j) {
        v[j].x = expf(v[j].x - m); v[j].y = expf(v[j].y - m);
        v[j].z = expf(v[j].z - m); v[j].w = expf(v[j].w - m);
        sum += v[j].x + v[j].y + v[j].z + v[j].w;
    }
    #pragma unroll
    for (int o = 16; o > 0; o >>= 1) sum += __shfl_xor_sync(0xffffffffu, sum, o);

    float inv = 1.0f / sum;
    #pragma unroll
    for (int j = 0; j < 8; ++j) {
        v[j].x *= inv; v[j].y *= inv; v[j].z *= inv; v[j].w *= inv;
        p[lane + 32 * j] = v[j];
    }
}

// ------------- PV: ctx = attn @ V --------------------------------------------
__global__ void __launch_bounds__(256)
pv_kernel(const float* __restrict__ S, const float* __restrict__ V,
          float* __restrict__ C)
{
    __shared__ float Ss[64][68];
    __shared__ float Vs[64][64];
    const int q0 = blockIdx.x * 64;
    const int bh = blockIdx.y;
    const int b = bh / HH, h = bh % HH;
    const int tid = threadIdx.x;
    const int ty = tid >> 4, tx = tid & 15;
    const int lr = tid >> 4, lc = (tid & 15) * 4;

    const float* Sb = S + ((size_t)bh << 20);
    float acc[4][4] = {};

    for (int kc = 0; kc < LL; kc += 64) {
        #pragma unroll
        for (int it = 0; it < 4; ++it) {
            int r = lr + it * 16;
            *(float4*)&Ss[r][lc] = *(const float4*)(Sb + (size_t)(q0 + r) * LL + kc + lc);
            *(float4*)&Vs[r][lc] = *(const float4*)(V + (size_t)(b * LL + kc + r) * DD + h * DKH + lc);
        }
        __syncthreads();
        #pragma unroll
        for (int k0 = 0; k0 < 64; k0 += 4) {
            float aq[4][4];
            #pragma unroll
            for (int i = 0; i < 4; ++i) *(float4*)aq[i] = *(float4*)&Ss[ty * 4 + i][k0];
            #pragma unroll
            for (int u = 0; u < 4; ++u) {
                float4 bv4 = *(float4*)&Vs[k0 + u][tx * 4];
                float b_[4] = {bv4.x, bv4.y, bv4.z, bv4.w};
                #pragma unroll
                for (int i = 0; i < 4; ++i)
                    #pragma unroll
                    for (int j = 0; j < 4; ++j)
                        acc[i][j] = fmaf(aq[i][u], b_[j], acc[i][j]);
            }
        }
        __syncthreads();
    }

    #pragma unroll
    for (int i = 0; i < 4; ++i) {
        size_t row = (size_t)(b * LL + q0 + ty * 4 + i);
        float o[4] = {acc[i][0], acc[i][1], acc[i][2], acc[i][3]};
        *(float4*)(C + row * DD + h * DKH + tx * 4) = *(float4*)o;
    }
}

// ------------- LayerNorm over last dim (768) ----------------------------------
__global__ void __launch_bounds__(256)
ln_kernel(const float* __restrict__ X, const float* __restrict__ g,
          const float* __restrict__ bt, float* __restrict__ O)
{
    const int row = blockIdx.x;
    const float* x = X + (size_t)row * DD;
    const int tid = threadIdx.x;

    float v[3];
    #pragma unroll
    for (int i = 0; i < 3; ++i) v[i] = x[tid + i * 256];

    __shared__ float red[256];
    float s = v[0] + v[1] + v[2];
    red[tid] = s; __syncthreads();
    for (int st = 128; st > 0; st >>= 1) {
        if (tid < st) red[tid] += red[tid + st];
        __syncthreads();
    }
    float mean = red[0] * (1.0f / DD);
    __syncthreads();

    float d0 = v[0] - mean, d1 = v[1] - mean, d2 = v[2] - mean;
    red[tid] = d0 * d0 + d1 * d1 + d2 * d2; __syncthreads();
    for (int st = 128; st > 0; st >>= 1) {
        if (tid < st) red[tid] += red[tid + st];
        __syncthreads();
    }
    float var = red[0] * (1.0f / DD);
    float inv = rsqrtf(var + 1e-5f);

    float* o = O + (size_t)row * DD;
    #pragma unroll
    for (int i = 0; i < 3; ++i) {
        int c = tid + i * 256;
        o[c] = (v[i] - mean) * inv * g[c] + bt[c];
    }
}

// ------------------------------- launch ---------------------------------------
extern "C" void kernel_launch(void* const* d_in, const int* in_sizes, int n_in,
                              void* d_out, int out_size)
{
    const float* tokens = (const float*)d_in[0];
    const float* pos    = (const float*)d_in[1];
    const float* pmask  = (const float*)d_in[2];
    const float* amask  = (const float*)d_in[3];
    const unsigned char* pad = (const unsigned char*)d_in[4];
    const float* Wq = (const float*)d_in[5];
    const float* bq = (const float*)d_in[6];
    const float* Wk = (const float*)d_in[7];
    const float* bk = (const float*)d_in[8];
    const float* Wv = (const float*)d_in[9];
    const float* bv = (const float*)d_in[10];
    const float* Wo = (const float*)d_in[11];
    const float* bo = (const float*)d_in[12];
    const float* table = (const float*)d_in[13];
    const float* W1 = (const float*)d_in[14];
    const float* b1 = (const float*)d_in[15];
    const float* W2 = (const float*)d_in[16];
    const float* b2 = (const float*)d_in[17];
    const float* ln1g = (const float*)d_in[18];
    const float* ln1b = (const float*)d_in[19];
    const float* ln2g = (const float*)d_in[20];
    const float* ln2b = (const float*)d_in[21];
    float* out = (float*)d_out;

    float *Qb, *Kb, *Vb, *Sb, *Cb, *Pb, *Tb, *Fb;
    cudaGetSymbolAddress((void**)&Qb, g_Q);
    cudaGetSymbolAddress((void**)&Kb, g_K);
    cudaGetSymbolAddress((void**)&Vb, g_V);
    cudaGetSymbolAddress((void**)&Sb, g_S);
    cudaGetSymbolAddress((void**)&Cb, g_ctx);
    cudaGetSymbolAddress((void**)&Pb, g_pre);
    cudaGetSymbolAddress((void**)&Tb, g_t1);
    cudaGetSymbolAddress((void**)&Fb, g_ff);

    dim3 gD(DD / 128, BL / 128);     // 6 x 32
    dim3 gF(FF / 128, BL / 128);     // 24 x 32

    gemm128<0><<<gD, 256>>>(tokens, Wq, bq, nullptr, Qb, DD, DD);
    gemm128<0><<<gD, 256>>>(tokens, Wk, bk, nullptr, Kb, DD, DD);
    gemm128<0><<<gD, 256>>>(tokens, Wv, bv, nullptr, Vb, DD, DD);

    dim3 gs(LL / 64, LL / 64, BB * HH);
    scores_kernel<<<gs, 256>>>(Qb, Kb, pos, pmask, amask, pad, table, Sb);

    softmax_kernel<<<(BB * HH * LL) / 8, 256>>>(Sb);

    dim3 gp(LL / 64, BB * HH);
    pv_kernel<<<gp, 256>>>(Sb, Vb, Cb);

    gemm128<2><<<gD, 256>>>(Cb, Wo, bo, tokens, Pb, DD, DD);
    ln_kernel<<<BL, 256>>>(Pb, ln1g, ln1b, Tb);

    gemm128<1><<<gF, 256>>>(Tb, W1, b1, nullptr, Fb, DD, FF);
    gemm128<2><<<gD, 256>>>(Fb, W2, b2, Tb, Pb, FF, DD);
    ln_kernel<<<BL, 256>>>(Pb, ln2g, ln2b, out);
}

// round 4
// speedup vs baseline: 1.8868x; 1.7507x over previous
#include <cuda_runtime.h>
#include <cuda_bf16.h>
#include <math.h>
#include <stdint.h>

#define BB   4
#define LL   1024
#define BL   4096
#define DD   768
#define HH   12
#define DKH  64
#define FF   3072
#define MDIST 100
#define TBL  201

// ---------------- fp32 scratch ----------------
__device__ float g_Q[BL * DD];
__device__ float g_K[BL * DD];
__device__ float g_V[BL * DD];
__device__ float g_S[(size_t)BB * HH * LL * LL];
__device__ float g_ctx[BL * DD];
__device__ float g_pre[BL * DD];
__device__ float g_t1[BL * DD];
__device__ float g_ff[BL * FF];

// ---------------- bf16 transposed/split weights ----------------
__device__ __align__(16) __nv_bfloat16 g_wqh[DD * DD], g_wql[DD * DD];
__device__ __align__(16) __nv_bfloat16 g_wkh[DD * DD], g_wkl[DD * DD];
__device__ __align__(16) __nv_bfloat16 g_wvh[DD * DD], g_wvl[DD * DD];
__device__ __align__(16) __nv_bfloat16 g_woh[DD * DD], g_wol[DD * DD];
__device__ __align__(16) __nv_bfloat16 g_w1h[(size_t)DD * FF], g_w1l[(size_t)DD * FF];
__device__ __align__(16) __nv_bfloat16 g_w2h[(size_t)DD * FF], g_w2l[(size_t)DD * FF];

// =================== helpers ===================
__device__ __forceinline__ uint32_t smem_u32(const void* p) {
    uint32_t a;
    asm("{ .reg .u64 t; cvta.to.shared.u64 t, %1; cvt.u32.u64 %0, t; }" : "=r"(a) : "l"(p));
    return a;
}
__device__ __forceinline__ void ldsm4(uint32_t* r, uint32_t addr) {
    asm volatile("ldmatrix.sync.aligned.m8n8.x4.shared.b16 {%0,%1,%2,%3}, [%4];"
        : "=r"(r[0]), "=r"(r[1]), "=r"(r[2]), "=r"(r[3]) : "r"(addr));
}
__device__ __forceinline__ void mma16816(float* d, const uint32_t* a, const uint32_t* b) {
    asm volatile("mma.sync.aligned.m16n8k16.row.col.f32.bf16.bf16.f32 "
        "{%0,%1,%2,%3}, {%4,%5,%6,%7}, {%8,%9}, {%0,%1,%2,%3};"
        : "+f"(d[0]), "+f"(d[1]), "+f"(d[2]), "+f"(d[3])
        : "r"(a[0]), "r"(a[1]), "r"(a[2]), "r"(a[3]), "r"(b[0]), "r"(b[1]));
}

// W [K][N] fp32  ->  WT_h/WT_l [N][K] bf16 (hi/lo split)
__global__ void __launch_bounds__(256)
cvt_wT(const float* __restrict__ W, __nv_bfloat16* __restrict__ TH,
       __nv_bfloat16* __restrict__ TL, int K, int N)
{
    __shared__ float t[32][33];
    const int n0 = blockIdx.x * 32, k0 = blockIdx.y * 32;
    const int tx = threadIdx.x & 31, ty = threadIdx.x >> 5;
    #pragma unroll
    for (int i = 0; i < 4; ++i)
        t[ty + 8 * i][tx] = W[(size_t)(k0 + ty + 8 * i) * N + n0 + tx];
    __syncthreads();
    #pragma unroll
    for (int i = 0; i < 4; ++i) {
        float x = t[tx][ty + 8 * i];
        __nv_bfloat16 h = __float2bfloat16(x);
        size_t o = (size_t)(n0 + ty + 8 * i) * K + k0 + tx;
        TH[o] = h;
        TL[o] = __float2bfloat16(x - __bfloat162float(h));
    }
}

// =================== mma.sync bf16-split GEMM ===================
// C[M,N] = A[M,K](fp32, split in-kernel) @ (Bh+Bl)^T, B* pre-transposed [N][K]
// EPI: 0 = +bias ; 1 = +bias,relu ; 2 = +bias,+residual
#define AST 40   // smem row stride in bf16 (80 B, 16B-aligned, ldmatrix conflict-free)

template<int EPI>
__global__ void __launch_bounds__(256)
gemm_mma(const float* __restrict__ A,
         const __nv_bfloat16* __restrict__ Bh, const __nv_bfloat16* __restrict__ Bl,
         const float* __restrict__ bias, const float* __restrict__ res,
         float* __restrict__ C, int K, int N)
{
    __shared__ __nv_bfloat16 sAh[128 * AST];
    __shared__ __nv_bfloat16 sAl[128 * AST];
    __shared__ __nv_bfloat16 sBh[128 * AST];
    __shared__ __nv_bfloat16 sBl[128 * AST];

    const int tid = threadIdx.x, wid = tid >> 5, lane = tid & 31;
    const int m0 = blockIdx.y * 128, n0 = blockIdx.x * 128;
    const int wm = (wid >> 2) * 64;      // warp m-offset (2 warps)
    const int wn = (wid & 3) * 32;       // warp n-offset (4 warps)

    float acc[4][4][4] = {};             // [mi][ni][frag]

    // per-thread load coords
    const int ar = tid >> 1;                  // A rows via 2 iters of (tid, tid+256)? no:
    (void)ar;
    // A: 128 rows x 32 fp32 = 1024 float4 -> 4 iters
    // B: 128 rows x 32 bf16 = 512 uint4  -> 2 iters (hi & lo each)

    float4 pa[4];
    uint4  pbh[2], pbl[2];

    const float* Ap = A + (size_t)m0 * K;
    const __nv_bfloat16* Bhp = Bh + (size_t)n0 * K;
    const __nv_bfloat16* Blp = Bl + (size_t)n0 * K;

    auto fetch = [&](int k0) {
        #pragma unroll
        for (int it = 0; it < 4; ++it) {
            int idx = tid + it * 256;
            int row = idx >> 3, g = idx & 7;
            pa[it] = *(const float4*)(Ap + (size_t)row * K + k0 + g * 4);
        }
        #pragma unroll
        for (int it = 0; it < 2; ++it) {
            int idx = tid + it * 256;
            int row = idx >> 2, g = idx & 3;
            size_t go = (size_t)row * K + k0 + g * 8;
            pbh[it] = *(const uint4*)(Bhp + go);
            pbl[it] = *(const uint4*)(Blp + go);
        }
    };
    auto stage = [&]() {
        #pragma unroll
        for (int it = 0; it < 4; ++it) {
            int idx = tid + it * 256;
            int row = idx >> 3, g = idx & 7;
            float v[4] = {pa[it].x, pa[it].y, pa[it].z, pa[it].w};
            __nv_bfloat16 h[4], l[4];
            #pragma unroll
            for (int u = 0; u < 4; ++u) {
                h[u] = __float2bfloat16(v[u]);
                l[u] = __float2bfloat16(v[u] - __bfloat162float(h[u]));
            }
            *(uint2*)&sAh[row * AST + g * 4] = *(uint2*)h;
            *(uint2*)&sAl[row * AST + g * 4] = *(uint2*)l;
        }
        #pragma unroll
        for (int it = 0; it < 2; ++it) {
            int idx = tid + it * 256;
            int row = idx >> 2, g = idx & 3;
            *(uint4*)&sBh[row * AST + g * 8] = pbh[it];
            *(uint4*)&sBl[row * AST + g * 8] = pbl[it];
        }
    };

    // ldmatrix lane addressing (element offsets within tile, bf16 units)
    const int a_row = wm + (lane & 15);
    const int a_kof = (lane >> 4) << 3;
    const int b_row = wn + ((lane >> 4) << 3) + (lane & 7);
    const int b_kof = ((lane >> 3) & 1) << 3;

    const uint32_t sAh_b = smem_u32(sAh), sAl_b = smem_u32(sAl);
    const uint32_t sBh_b = smem_u32(sBh), sBl_b = smem_u32(sBl);

    fetch(0);
    stage();
    __syncthreads();

    const int ns = K >> 5;
    for (int s = 0; s < ns; ++s) {
        if (s + 1 < ns) fetch((s + 1) << 5);

        #pragma unroll
        for (int kstep = 0; kstep < 2; ++kstep) {
            const int kk = kstep * 16;
            uint32_t afh[4][4], afl[4][4];
            #pragma unroll
            for (int mi = 0; mi < 4; ++mi) {
                uint32_t off = (uint32_t)((a_row + mi * 16) * AST + kk + a_kof) * 2;
                ldsm4(afh[mi], sAh_b + off);
                ldsm4(afl[mi], sAl_b + off);
            }
            uint32_t bfh[2][4], bfl[2][4];
            #pragma unroll
            for (int g = 0; g < 2; ++g) {
                uint32_t off = (uint32_t)((b_row + g * 16) * AST + kk + b_kof) * 2;
                ldsm4(bfh[g], sBh_b + off);
                ldsm4(bfl[g], sBl_b + off);
            }
            #pragma unroll
            for (int mi = 0; mi < 4; ++mi)
                #pragma unroll
                for (int ni = 0; ni < 4; ++ni) {
                    const uint32_t* bh_ = &bfh[ni >> 1][(ni & 1) * 2];
                    const uint32_t* bl_ = &bfl[ni >> 1][(ni & 1) * 2];
                    mma16816(acc[mi][ni], afh[mi], bh_);
                    mma16816(acc[mi][ni], afh[mi], bl_);
                    mma16816(acc[mi][ni], afl[mi], bh_);
                }
        }

        __syncthreads();
        if (s + 1 < ns) {
            stage();
            __syncthreads();
        }
    }

    // epilogue: c-frag mapping: rows l/4 and l/4+8; cols 2*(l%4), +1
    const int er = lane >> 2, ec = (lane & 3) * 2;
    #pragma unroll
    for (int mi = 0; mi < 4; ++mi) {
        #pragma unroll
        for (int hrow = 0; hrow < 2; ++hrow) {
            int row = m0 + wm + mi * 16 + er + hrow * 8;
            float* cp = C + (size_t)row * N;
            const float* rp = res + (size_t)row * N;
            #pragma unroll
            for (int ni = 0; ni < 4; ++ni) {
                int col = n0 + wn + ni * 8 + ec;
                float v0 = acc[mi][ni][hrow * 2 + 0] + bias[col];
                float v1 = acc[mi][ni][hrow * 2 + 1] + bias[col + 1];
                if (EPI == 1) { v0 = fmaxf(v0, 0.0f); v1 = fmaxf(v1, 0.0f); }
                if (EPI == 2) { v0 += rp[col]; v1 += rp[col + 1]; }
                float2 o = {v0, v1};
                *(float2*)(cp + col) = o;
            }
        }
    }
}

// ------------- scores: S = QK^T/8 + relpos bias, masked ----------------------
__global__ void __launch_bounds__(256)
scores_kernel(const float* __restrict__ Q, const float* __restrict__ Kb,
              const float* __restrict__ pos, const float* __restrict__ pmask,
              const float* __restrict__ amask, const unsigned char* __restrict__ pad,
              const float* __restrict__ table, float* __restrict__ S)
{
    __shared__ float Qs[64][65];
    __shared__ float Ks[64][65];
    __shared__ float pxq[64], pyq[64], pmq[64];
    __shared__ float pxk[64], pyk[64], pmk[64];

    const int k0 = blockIdx.x * 64;
    const int q0 = blockIdx.y * 64;
    const int bh = blockIdx.z;
    const int b = bh / HH, h = bh % HH;
    const int tid = threadIdx.x;

    #pragma unroll
    for (int it = 0; it < 4; ++it) {
        int li = tid + it * 256;
        int r = li >> 4, c4 = li & 15;
        float4 q4 = *(const float4*)(Q + ((size_t)(b * LL + q0 + r)) * DD + h * DKH + c4 * 4);
        Qs[r][c4 * 4 + 0] = q4.x; Qs[r][c4 * 4 + 1] = q4.y;
        Qs[r][c4 * 4 + 2] = q4.z; Qs[r][c4 * 4 + 3] = q4.w;
        float4 k4 = *(const float4*)(Kb + ((size_t)(b * LL + k0 + r)) * DD + h * DKH + c4 * 4);
        Ks[r][c4 * 4 + 0] = k4.x; Ks[r][c4 * 4 + 1] = k4.y;
        Ks[r][c4 * 4 + 2] = k4.z; Ks[r][c4 * 4 + 3] = k4.w;
    }
    if (tid < 64) {
        int l = b * LL + q0 + tid;
        pxq[tid] = pos[(size_t)l * 2 + 0];
        pyq[tid] = pos[(size_t)l * 2 + 1];
        pmq[tid] = pmask[l];
    } else if (tid < 128) {
        int t = tid - 64;
        int l = b * LL + k0 + t;
        pxk[t] = pos[(size_t)l * 2 + 0];
        pyk[t] = pos[(size_t)l * 2 + 1];
        pmk[t] = pmask[l];
    }
    __syncthreads();

    const int ty = tid >> 4, tx = tid & 15;
    float acc[4][4] = {};
    #pragma unroll 8
    for (int d = 0; d < DKH; ++d) {
        float a_[4], b_[4];
        #pragma unroll
        for (int i = 0; i < 4; ++i) a_[i] = Qs[ty * 4 + i][d];
        #pragma unroll
        for (int j = 0; j < 4; ++j) b_[j] = Ks[tx * 4 + j][d];
        #pragma unroll
        for (int i = 0; i < 4; ++i)
            #pragma unroll
            for (int j = 0; j < 4; ++j)
                acc[i][j] = fmaf(a_[i], b_[j], acc[i][j]);
    }

    #pragma unroll
    for (int i = 0; i < 4; ++i) {
        int qi = ty * 4 + i;
        int qg = q0 + qi;
        float4 am = *(const float4*)(amask + (size_t)(b * LL + qg) * LL + k0 + tx * 4);
        float amv[4] = {am.x, am.y, am.z, am.w};
        float o[4];
        #pragma unroll
        for (int j = 0; j < 4; ++j) {
            int kj = tx * 4 + j;
            int kg = k0 + kj;
            float s = acc[i][j] * 0.125f;
            float ddx = rintf(pxq[qi] - pxk[kj]);
            float ddy = rintf(pyq[qi] - pyk[kj]);
            ddx = fminf(fmaxf(ddx, -(float)MDIST), (float)MDIST);
            ddy = fminf(fmaxf(ddy, -(float)MDIST), (float)MDIST);
            int dx = (int)ddx + MDIST;
            int dy = (int)ddy + MDIST;
            float bias = table[((size_t)h * TBL + dy) * TBL + dx] * (pmq[qi] * pmk[kj]);
            s += bias;
            bool inval = (amv[j] == 0.0f) || (pad[b * LL + kg] != 0);
            o[j] = inval ? -1e9f : s;
        }
        *(float4*)(S + ((size_t)bh << 20) + (size_t)qg * LL + k0 + tx * 4) = *(float4*)o;
    }
}

// ------------- softmax: warp per row ------------------------------------------
__global__ void __launch_bounds__(256)
softmax_kernel(float* __restrict__ S)
{
    const int w = threadIdx.x >> 5, lane = threadIdx.x & 31;
    const size_t row = (size_t)blockIdx.x * 8 + w;
    float4* p = (float4*)(S + row * LL);
    float4 v[8];
    #pragma unroll
    for (int j = 0; j < 8; ++j) v[j] = p[lane + 32 * j];

    float m = -1e30f;
    #pragma unroll
    for (int j = 0; j < 8; ++j)
        m = fmaxf(m, fmaxf(fmaxf(v[j].x, v[j].y), fmaxf(v[j].z, v[j].w)));
    #pragma unroll
    for (int o = 16; o > 0; o >>= 1) m = fmaxf(m, __shfl_xor_sync(0xffffffffu, m, o));

    float sum = 0.0f;
    #pragma unroll
    for (int j = 0; j < 8; ++j) {
        v[j].x = expf(v[j].x - m); v[j].y = expf(v[j].y - m);
        v[j].z = expf(v[j].z - m); v[j].w = expf(v[j].w - m);
        sum += v[j].x + v[j].y + v[j].z + v[j].w;
    }
    #pragma unroll
    for (int o = 16; o > 0; o >>= 1) sum += __shfl_xor_sync(0xffffffffu, sum, o);

    float inv = 1.0f / sum;
    #pragma unroll
    for (int j = 0; j < 8; ++j) {
        v[j].x *= inv; v[j].y *= inv; v[j].z *= inv; v[j].w *= inv;
        p[lane + 32 * j] = v[j];
    }
}

// ------------- PV: ctx = attn @ V --------------------------------------------
__global__ void __launch_bounds__(256)
pv_kernel(const float* __restrict__ S, const float* __restrict__ V,
          float* __restrict__ C)
{
    __shared__ float Ss[64][68];
    __shared__ float Vs[64][64];
    const int q0 = blockIdx.x * 64;
    const int bh = blockIdx.y;
    const int b = bh / HH, h = bh % HH;
    const int tid = threadIdx.x;
    const int ty = tid >> 4, tx = tid & 15;
    const int lr = tid >> 4, lc = (tid & 15) * 4;

    const float* Sb = S + ((size_t)bh << 20);
    float acc[4][4] = {};

    for (int kc = 0; kc < LL; kc += 64) {
        #pragma unroll
        for (int it = 0; it < 4; ++it) {
            int rr = lr + it * 16;
            *(float4*)&Ss[rr][lc] = *(const float4*)(Sb + (size_t)(q0 + rr) * LL + kc + lc);
            *(float4*)&Vs[rr][lc] = *(const float4*)(V + (size_t)(b * LL + kc + rr) * DD + h * DKH + lc);
        }
        __syncthreads();
        #pragma unroll
        for (int k0 = 0; k0 < 64; k0 += 4) {
            float aq[4][4];
            #pragma unroll
            for (int i = 0; i < 4; ++i) *(float4*)aq[i] = *(float4*)&Ss[ty * 4 + i][k0];
            #pragma unroll
            for (int u = 0; u < 4; ++u) {
                float4 bv4 = *(float4*)&Vs[k0 + u][tx * 4];
                float b_[4] = {bv4.x, bv4.y, bv4.z, bv4.w};
                #pragma unroll
                for (int i = 0; i < 4; ++i)
                    #pragma unroll
                    for (int j = 0; j < 4; ++j)
                        acc[i][j] = fmaf(aq[i][u], b_[j], acc[i][j]);
            }
        }
        __syncthreads();
    }

    #pragma unroll
    for (int i = 0; i < 4; ++i) {
        size_t row = (size_t)(b * LL + q0 + ty * 4 + i);
        float o[4] = {acc[i][0], acc[i][1], acc[i][2], acc[i][3]};
        *(float4*)(C + row * DD + h * DKH + tx * 4) = *(float4*)o;
    }
}

// ------------- LayerNorm over last dim (768) ----------------------------------
__global__ void __launch_bounds__(256)
ln_kernel(const float* __restrict__ X, const float* __restrict__ g,
          const float* __restrict__ bt, float* __restrict__ O)
{
    const int row = blockIdx.x;
    const float* x = X + (size_t)row * DD;
    const int tid = threadIdx.x;

    float v[3];
    #pragma unroll
    for (int i = 0; i < 3; ++i) v[i] = x[tid + i * 256];

    __shared__ float red[256];
    float s = v[0] + v[1] + v[2];
    red[tid] = s; __syncthreads();
    for (int st = 128; st > 0; st >>= 1) {
        if (tid < st) red[tid] += red[tid + st];
        __syncthreads();
    }
    float mean = red[0] * (1.0f / DD);
    __syncthreads();

    float d0 = v[0] - mean, d1 = v[1] - mean, d2 = v[2] - mean;
    red[tid] = d0 * d0 + d1 * d1 + d2 * d2; __syncthreads();
    for (int st = 128; st > 0; st >>= 1) {
        if (tid < st) red[tid] += red[tid + st];
        __syncthreads();
    }
    float var = red[0] * (1.0f / DD);
    float inv = rsqrtf(var + 1e-5f);

    float* o = O + (size_t)row * DD;
    #pragma unroll
    for (int i = 0; i < 3; ++i) {
        int c = tid + i * 256;
        o[c] = (v[i] - mean) * inv * g[c] + bt[c];
    }
}

// ------------------------------- launch ---------------------------------------
extern "C" void kernel_launch(void* const* d_in, const int* in_sizes, int n_in,
                              void* d_out, int out_size)
{
    const float* tokens = (const float*)d_in[0];
    const float* pos    = (const float*)d_in[1];
    const float* pmask  = (const float*)d_in[2];
    const float* amask  = (const float*)d_in[3];
    const unsigned char* pad = (const unsigned char*)d_in[4];
    const float* Wq = (const float*)d_in[5];
    const float* bq = (const float*)d_in[6];
    const float* Wk = (const float*)d_in[7];
    const float* bk = (const float*)d_in[8];
    const float* Wv = (const float*)d_in[9];
    const float* bv = (const float*)d_in[10];
    const float* Wo = (const float*)d_in[11];
    const float* bo = (const float*)d_in[12];
    const float* table = (const float*)d_in[13];
    const float* W1 = (const float*)d_in[14];
    const float* b1 = (const float*)d_in[15];
    const float* W2 = (const float*)d_in[16];
    const float* b2 = (const float*)d_in[17];
    const float* ln1g = (const float*)d_in[18];
    const float* ln1b = (const float*)d_in[19];
    const float* ln2g = (const float*)d_in[20];
    const float* ln2b = (const float*)d_in[21];
    float* out = (float*)d_out;

    float *Qb, *Kb, *Vb, *Sb, *Cb, *Pb, *Tb, *Fb;
    cudaGetSymbolAddress((void**)&Qb, g_Q);
    cudaGetSymbolAddress((void**)&Kb, g_K);
    cudaGetSymbolAddress((void**)&Vb, g_V);
    cudaGetSymbolAddress((void**)&Sb, g_S);
    cudaGetSymbolAddress((void**)&Cb, g_ctx);
    cudaGetSymbolAddress((void**)&Pb, g_pre);
    cudaGetSymbolAddress((void**)&Tb, g_t1);
    cudaGetSymbolAddress((void**)&Fb, g_ff);

    __nv_bfloat16 *wqh, *wql, *wkh, *wkl, *wvh, *wvl, *woh, *wol, *w1h, *w1l, *w2h, *w2l;
    cudaGetSymbolAddress((void**)&wqh, g_wqh); cudaGetSymbolAddress((void**)&wql, g_wql);
    cudaGetSymbolAddress((void**)&wkh, g_wkh); cudaGetSymbolAddress((void**)&wkl, g_wkl);
    cudaGetSymbolAddress((void**)&wvh, g_wvh); cudaGetSymbolAddress((void**)&wvl, g_wvl);
    cudaGetSymbolAddress((void**)&woh, g_woh); cudaGetSymbolAddress((void**)&wol, g_wol);
    cudaGetSymbolAddress((void**)&w1h, g_w1h); cudaGetSymbolAddress((void**)&w1l, g_w1l);
    cudaGetSymbolAddress((void**)&w2h, g_w2h); cudaGetSymbolAddress((void**)&w2l, g_w2l);

    // weight transpose + split (bf16 hi/lo)
    dim3 gw(DD / 32, DD / 32);
    cvt_wT<<<gw, 256>>>(Wq, wqh, wql, DD, DD);
    cvt_wT<<<gw, 256>>>(Wk, wkh, wkl, DD, DD);
    cvt_wT<<<gw, 256>>>(Wv, wvh, wvl, DD, DD);
    cvt_wT<<<gw, 256>>>(Wo, woh, wol, DD, DD);
    cvt_wT<<<dim3(FF / 32, DD / 32), 256>>>(W1, w1h, w1l, DD, FF);
    cvt_wT<<<dim3(DD / 32, FF / 32), 256>>>(W2, w2h, w2l, FF, DD);

    dim3 gD(DD / 128, BL / 128);     // 6 x 32
    dim3 gF(FF / 128, BL / 128);     // 24 x 32

    gemm_mma<0><<<gD, 256>>>(tokens, wqh, wql, bq, nullptr, Qb, DD, DD);
    gemm_mma<0><<<gD, 256>>>(tokens, wkh, wkl, bk, nullptr, Kb, DD, DD);
    gemm_mma<0><<<gD, 256>>>(tokens, wvh, wvl, bv, nullptr, Vb, DD, DD);

    dim3 gs(LL / 64, LL / 64, BB * HH);
    scores_kernel<<<gs, 256>>>(Qb, Kb, pos, pmask, amask, pad, table, Sb);
    softmax_kernel<<<(BB * HH * LL) / 8, 256>>>(Sb);
    dim3 gp(LL / 64, BB * HH);
    pv_kernel<<<gp, 256>>>(Sb, Vb, Cb);

    gemm_mma<2><<<gD, 256>>>(Cb, woh, wol, bo, tokens, Pb, DD, DD);
    ln_kernel<<<BL, 256>>>(Pb, ln1g, ln1b, Tb);

    gemm_mma<1><<<gF, 256>>>(Tb, w1h, w1l, b1, nullptr, Fb, DD, FF);
    gemm_mma<2><<<gD, 256>>>(Fb, w2h, w2l, b2, Tb, Pb, FF, DD);
    ln_kernel<<<BL, 256>>>(Pb, ln2g, ln2b, out);
}

// round 5
// speedup vs baseline: 2.4451x; 1.2959x over previous
#include <cuda_runtime.h>
#include <cuda_bf16.h>
#include <math.h>
#include <stdint.h>

#define BB   4
#define LL   1024
#define BL   4096
#define DD   768
#define HH   12
#define DKH  64
#define FF   3072
#define MDIST 100
#define TBL  201

// ---------------- scratch ----------------
__device__ float g_ctx[BL * DD];
__device__ float g_pre[BL * DD];
__device__ float g_t1[BL * DD];
__device__ float g_ff[BL * FF];

// bf16 hi/lo split activations (QKV)
__device__ __align__(16) __nv_bfloat16 g_qh[BL * DD], g_ql[BL * DD];
__device__ __align__(16) __nv_bfloat16 g_kh[BL * DD], g_kl[BL * DD];
__device__ __align__(16) __nv_bfloat16 g_vh[BL * DD], g_vl[BL * DD];

// bf16 transposed/split weights
__device__ __align__(16) __nv_bfloat16 g_wqh[DD * DD], g_wql[DD * DD];
__device__ __align__(16) __nv_bfloat16 g_wkh[DD * DD], g_wkl[DD * DD];
__device__ __align__(16) __nv_bfloat16 g_wvh[DD * DD], g_wvl[DD * DD];
__device__ __align__(16) __nv_bfloat16 g_woh[DD * DD], g_wol[DD * DD];
__device__ __align__(16) __nv_bfloat16 g_w1h[(size_t)DD * FF], g_w1l[(size_t)DD * FF];
__device__ __align__(16) __nv_bfloat16 g_w2h[(size_t)DD * FF], g_w2l[(size_t)DD * FF];

// =================== helpers ===================
__device__ __forceinline__ uint32_t smem_u32(const void* p) {
    uint32_t a;
    asm("{ .reg .u64 t; cvta.to.shared.u64 t, %1; cvt.u32.u64 %0, t; }" : "=r"(a) : "l"(p));
    return a;
}
__device__ __forceinline__ void ldsm4(uint32_t* r, uint32_t addr) {
    asm volatile("ldmatrix.sync.aligned.m8n8.x4.shared.b16 {%0,%1,%2,%3}, [%4];"
        : "=r"(r[0]), "=r"(r[1]), "=r"(r[2]), "=r"(r[3]) : "r"(addr));
}
__device__ __forceinline__ void ldsm4t(uint32_t* r, uint32_t addr) {
    asm volatile("ldmatrix.sync.aligned.m8n8.x4.trans.shared.b16 {%0,%1,%2,%3}, [%4];"
        : "=r"(r[0]), "=r"(r[1]), "=r"(r[2]), "=r"(r[3]) : "r"(addr));
}
__device__ __forceinline__ void mma16816(float* d, const uint32_t* a, const uint32_t* b) {
    asm volatile("mma.sync.aligned.m16n8k16.row.col.f32.bf16.bf16.f32 "
        "{%0,%1,%2,%3}, {%4,%5,%6,%7}, {%8,%9}, {%0,%1,%2,%3};"
        : "+f"(d[0]), "+f"(d[1]), "+f"(d[2]), "+f"(d[3])
        : "r"(a[0]), "r"(a[1]), "r"(a[2]), "r"(a[3]), "r"(b[0]), "r"(b[1]));
}
__device__ __forceinline__ void split2(float a, float b, uint32_t& hi, uint32_t& lo) {
    __nv_bfloat16 ha = __float2bfloat16(a), hb = __float2bfloat16(b);
    __nv_bfloat16 la = __float2bfloat16(a - __bfloat162float(ha));
    __nv_bfloat16 lb = __float2bfloat16(b - __bfloat162float(hb));
    __nv_bfloat162 th, tl;
    th.x = ha; th.y = hb; tl.x = la; tl.y = lb;
    hi = *(uint32_t*)&th; lo = *(uint32_t*)&tl;
}

// W [K][N] fp32  ->  WT_h/WT_l [N][K] bf16 (hi/lo split)
__global__ void __launch_bounds__(256)
cvt_wT(const float* __restrict__ W, __nv_bfloat16* __restrict__ TH,
       __nv_bfloat16* __restrict__ TL, int K, int N)
{
    __shared__ float t[32][33];
    const int n0 = blockIdx.x * 32, k0 = blockIdx.y * 32;
    const int tx = threadIdx.x & 31, ty = threadIdx.x >> 5;
    #pragma unroll
    for (int i = 0; i < 4; ++i)
        t[ty + 8 * i][tx] = W[(size_t)(k0 + ty + 8 * i) * N + n0 + tx];
    __syncthreads();
    #pragma unroll
    for (int i = 0; i < 4; ++i) {
        float x = t[tx][ty + 8 * i];
        __nv_bfloat16 h = __float2bfloat16(x);
        size_t o = (size_t)(n0 + ty + 8 * i) * K + k0 + tx;
        TH[o] = h;
        TL[o] = __float2bfloat16(x - __bfloat162float(h));
    }
}

// =================== mma.sync bf16-split GEMM ===================
// EPI: 0 = +bias ; 1 = +bias,relu ; 2 = +bias,+residual ; 3 = +bias -> bf16 h/l
#define AST 40

template<int EPI>
__global__ void __launch_bounds__(256)
gemm_mma(const float* __restrict__ A,
         const __nv_bfloat16* __restrict__ Bh, const __nv_bfloat16* __restrict__ Bl,
         const float* __restrict__ bias, const float* __restrict__ res,
         float* __restrict__ C,
         __nv_bfloat16* __restrict__ Ch, __nv_bfloat16* __restrict__ Cl,
         int K, int N)
{
    __shared__ __nv_bfloat16 sAh[128 * AST];
    __shared__ __nv_bfloat16 sAl[128 * AST];
    __shared__ __nv_bfloat16 sBh[128 * AST];
    __shared__ __nv_bfloat16 sBl[128 * AST];

    const int tid = threadIdx.x, wid = tid >> 5, lane = tid & 31;
    const int m0 = blockIdx.y * 128, n0 = blockIdx.x * 128;
    const int wm = (wid >> 2) * 64;
    const int wn = (wid & 3) * 32;

    float acc[4][4][4] = {};

    float4 pa[4];
    uint4  pbh[2], pbl[2];

    const float* Ap = A + (size_t)m0 * K;
    const __nv_bfloat16* Bhp = Bh + (size_t)n0 * K;
    const __nv_bfloat16* Blp = Bl + (size_t)n0 * K;

    auto fetch = [&](int k0) {
        #pragma unroll
        for (int it = 0; it < 4; ++it) {
            int idx = tid + it * 256;
            int row = idx >> 3, g = idx & 7;
            pa[it] = *(const float4*)(Ap + (size_t)row * K + k0 + g * 4);
        }
        #pragma unroll
        for (int it = 0; it < 2; ++it) {
            int idx = tid + it * 256;
            int row = idx >> 2, g = idx & 3;
            size_t go = (size_t)row * K + k0 + g * 8;
            pbh[it] = *(const uint4*)(Bhp + go);
            pbl[it] = *(const uint4*)(Blp + go);
        }
    };
    auto stage = [&]() {
        #pragma unroll
        for (int it = 0; it < 4; ++it) {
            int idx = tid + it * 256;
            int row = idx >> 3, g = idx & 7;
            float v[4] = {pa[it].x, pa[it].y, pa[it].z, pa[it].w};
            __nv_bfloat16 h[4], l[4];
            #pragma unroll
            for (int u = 0; u < 4; ++u) {
                h[u] = __float2bfloat16(v[u]);
                l[u] = __float2bfloat16(v[u] - __bfloat162float(h[u]));
            }
            *(uint2*)&sAh[row * AST + g * 4] = *(uint2*)h;
            *(uint2*)&sAl[row * AST + g * 4] = *(uint2*)l;
        }
        #pragma unroll
        for (int it = 0; it < 2; ++it) {
            int idx = tid + it * 256;
            int row = idx >> 2, g = idx & 3;
            *(uint4*)&sBh[row * AST + g * 8] = pbh[it];
            *(uint4*)&sBl[row * AST + g * 8] = pbl[it];
        }
    };

    const int a_row = wm + (lane & 15);
    const int a_kof = (lane >> 4) << 3;
    const int b_row = wn + ((lane >> 4) << 3) + (lane & 7);
    const int b_kof = ((lane >> 3) & 1) << 3;

    const uint32_t sAh_b = smem_u32(sAh), sAl_b = smem_u32(sAl);
    const uint32_t sBh_b = smem_u32(sBh), sBl_b = smem_u32(sBl);

    fetch(0);
    stage();
    __syncthreads();

    const int ns = K >> 5;
    for (int s = 0; s < ns; ++s) {
        if (s + 1 < ns) fetch((s + 1) << 5);

        #pragma unroll
        for (int kstep = 0; kstep < 2; ++kstep) {
            const int kk = kstep * 16;
            uint32_t afh[4][4], afl[4][4];
            #pragma unroll
            for (int mi = 0; mi < 4; ++mi) {
                uint32_t off = (uint32_t)((a_row + mi * 16) * AST + kk + a_kof) * 2;
                ldsm4(afh[mi], sAh_b + off);
                ldsm4(afl[mi], sAl_b + off);
            }
            uint32_t bfh[2][4], bfl[2][4];
            #pragma unroll
            for (int g = 0; g < 2; ++g) {
                uint32_t off = (uint32_t)((b_row + g * 16) * AST + kk + b_kof) * 2;
                ldsm4(bfh[g], sBh_b + off);
                ldsm4(bfl[g], sBl_b + off);
            }
            #pragma unroll
            for (int mi = 0; mi < 4; ++mi)
                #pragma unroll
                for (int ni = 0; ni < 4; ++ni) {
                    const uint32_t* bh_ = &bfh[ni >> 1][(ni & 1) * 2];
                    const uint32_t* bl_ = &bfl[ni >> 1][(ni & 1) * 2];
                    mma16816(acc[mi][ni], afh[mi], bh_);
                    mma16816(acc[mi][ni], afh[mi], bl_);
                    mma16816(acc[mi][ni], afl[mi], bh_);
                }
        }

        __syncthreads();
        if (s + 1 < ns) {
            stage();
            __syncthreads();
        }
    }

    const int er = lane >> 2, ec = (lane & 3) * 2;
    #pragma unroll
    for (int mi = 0; mi < 4; ++mi) {
        #pragma unroll
        for (int hrow = 0; hrow < 2; ++hrow) {
            int row = m0 + wm + mi * 16 + er + hrow * 8;
            float* cp = (EPI != 3) ? (C + (size_t)row * N) : nullptr;
            const float* rp = res + (size_t)row * N;
            #pragma unroll
            for (int ni = 0; ni < 4; ++ni) {
                int col = n0 + wn + ni * 8 + ec;
                float v0 = acc[mi][ni][hrow * 2 + 0] + bias[col];
                float v1 = acc[mi][ni][hrow * 2 + 1] + bias[col + 1];
                if (EPI == 1) { v0 = fmaxf(v0, 0.0f); v1 = fmaxf(v1, 0.0f); }
                if (EPI == 2) { v0 += rp[col]; v1 += rp[col + 1]; }
                if (EPI == 3) {
                    uint32_t hi, lo;
                    split2(v0, v1, hi, lo);
                    *(uint32_t*)(Ch + (size_t)row * N + col) = hi;
                    *(uint32_t*)(Cl + (size_t)row * N + col) = lo;
                } else {
                    float2 o = {v0, v1};
                    *(float2*)(cp + col) = o;
                }
            }
        }
    }
}

// =================== fused flash attention ===================
#define FST 72

__global__ void __launch_bounds__(128)
flash_kernel(const __nv_bfloat16* __restrict__ Qh, const __nv_bfloat16* __restrict__ Ql,
             const __nv_bfloat16* __restrict__ Kh, const __nv_bfloat16* __restrict__ Kl,
             const __nv_bfloat16* __restrict__ Vh, const __nv_bfloat16* __restrict__ Vl,
             const float* __restrict__ pos, const float* __restrict__ pmask,
             const float* __restrict__ amask, const unsigned char* __restrict__ pad,
             const float* __restrict__ table, float* __restrict__ ctx)
{
    __shared__ __nv_bfloat16 sKh[64 * FST], sKl[64 * FST];
    __shared__ __nv_bfloat16 sVh[64 * FST], sVl[64 * FST];
    __shared__ float pxq[64], pyq[64], pmq[64];
    __shared__ float pxk[64], pyk[64], pmk[64], padk[64];

    const int q0 = blockIdx.x * 64;
    const int bh = blockIdx.y;
    const int b = bh / HH, h = bh % HH;
    const int tid = threadIdx.x, wid = tid >> 5, lane = tid & 31;
    const float* tbl = table + (size_t)h * TBL * TBL;

    if (tid < 64) {
        int l = b * LL + q0 + tid;
        pxq[tid] = pos[2 * (size_t)l];
        pyq[tid] = pos[2 * (size_t)l + 1];
        pmq[tid] = pmask[l];
    }

    // stage Q (reuse K buffers) and load Q fragments to registers
    #pragma unroll
    for (int it = 0; it < 4; ++it) {
        int idx = tid + it * 128;
        int row = idx >> 3, g = idx & 7;
        size_t go = (size_t)(b * LL + q0 + row) * DD + h * DKH + g * 8;
        *(uint4*)&sKh[row * FST + g * 8] = *(const uint4*)(Qh + go);
        *(uint4*)&sKl[row * FST + g * 8] = *(const uint4*)(Ql + go);
    }
    __syncthreads();

    const uint32_t sKh_b = smem_u32(sKh), sKl_b = smem_u32(sKl);
    const uint32_t sVh_b = smem_u32(sVh), sVl_b = smem_u32(sVl);

    uint32_t qfh[4][4], qfl[4][4];
    {
        int a_row = wid * 16 + (lane & 15);
        int a_kof = (lane >> 4) << 3;
        #pragma unroll
        for (int j = 0; j < 4; ++j) {
            uint32_t off = (uint32_t)(a_row * FST + j * 16 + a_kof) * 2;
            ldsm4(qfh[j], sKh_b + off);
            ldsm4(qfl[j], sKl_b + off);
        }
    }
    __syncthreads();

    const int er = lane >> 2, ec = (lane & 3) * 2;
    const int qr0 = q0 + wid * 16 + er;
    float mrow[2] = {-1e30f, -1e30f}, lrow[2] = {0.f, 0.f};
    float accO[8][4] = {};

    for (int kt = 0; kt < 16; ++kt) {
        const int k0 = kt * 64;
        #pragma unroll
        for (int it = 0; it < 4; ++it) {
            int idx = tid + it * 128;
            int row = idx >> 3, g = idx & 7;
            size_t go = (size_t)(b * LL + k0 + row) * DD + h * DKH + g * 8;
            *(uint4*)&sKh[row * FST + g * 8] = *(const uint4*)(Kh + go);
            *(uint4*)&sKl[row * FST + g * 8] = *(const uint4*)(Kl + go);
            *(uint4*)&sVh[row * FST + g * 8] = *(const uint4*)(Vh + go);
            *(uint4*)&sVl[row * FST + g * 8] = *(const uint4*)(Vl + go);
        }
        if (tid < 64) {
            int l = b * LL + k0 + tid;
            pxk[tid] = pos[2 * (size_t)l];
            pyk[tid] = pos[2 * (size_t)l + 1];
            pmk[tid] = pmask[l];
            padk[tid] = pad[l] ? 1.f : 0.f;
        }
        __syncthreads();

        // ---- S = Q K^T (3-term split) ----
        float accS[8][4] = {};
        #pragma unroll
        for (int j = 0; j < 4; ++j) {
            #pragma unroll
            for (int g = 0; g < 4; ++g) {
                uint32_t kh[4], kl[4];
                int b_row = g * 16 + ((lane >> 4) << 3) + (lane & 7);
                uint32_t off = (uint32_t)(b_row * FST + j * 16 + (((lane >> 3) & 1) << 3)) * 2;
                ldsm4(kh, sKh_b + off);
                ldsm4(kl, sKl_b + off);
                mma16816(accS[2 * g],     qfh[j], kh);
                mma16816(accS[2 * g],     qfh[j], kl);
                mma16816(accS[2 * g],     qfl[j], kh);
                mma16816(accS[2 * g + 1], qfh[j], kh + 2);
                mma16816(accS[2 * g + 1], qfh[j], kl + 2);
                mma16816(accS[2 * g + 1], qfl[j], kh + 2);
            }
        }

        // ---- bias + mask + online softmax ----
        float pxr[2] = {pxq[wid * 16 + er], pxq[wid * 16 + er + 8]};
        float pyr[2] = {pyq[wid * 16 + er], pyq[wid * 16 + er + 8]};
        float pmr[2] = {pmq[wid * 16 + er], pmq[wid * 16 + er + 8]};
        float newm[2] = {mrow[0], mrow[1]};
        #pragma unroll
        for (int ni = 0; ni < 8; ++ni) {
            #pragma unroll
            for (int r = 0; r < 2; ++r) {
                int kj0 = ni * 8 + ec;
                float2 am = *(const float2*)(amask + (size_t)(b * LL + qr0 + 8 * r) * LL + k0 + kj0);
                #pragma unroll
                for (int u = 0; u < 2; ++u) {
                    int kj = kj0 + u;
                    float s = accS[ni][2 * r + u] * 0.125f;
                    float ddx = fminf(fmaxf(rintf(pxr[r] - pxk[kj]), -(float)MDIST), (float)MDIST);
                    float ddy = fminf(fmaxf(rintf(pyr[r] - pyk[kj]), -(float)MDIST), (float)MDIST);
                    int dx = (int)ddx + MDIST, dy = (int)ddy + MDIST;
                    s += tbl[dy * TBL + dx] * (pmr[r] * pmk[kj]);
                    float amv = (u == 0) ? am.x : am.y;
                    if (amv == 0.f || padk[kj] != 0.f) s = -1e9f;
                    accS[ni][2 * r + u] = s;
                    newm[r] = fmaxf(newm[r], s);
                }
            }
        }
        #pragma unroll
        for (int r = 0; r < 2; ++r) {
            newm[r] = fmaxf(newm[r], __shfl_xor_sync(0xffffffffu, newm[r], 1));
            newm[r] = fmaxf(newm[r], __shfl_xor_sync(0xffffffffu, newm[r], 2));
        }
        float alpha[2], psum[2] = {0.f, 0.f};
        #pragma unroll
        for (int r = 0; r < 2; ++r) {
            alpha[r] = expf(mrow[r] - newm[r]);
            mrow[r] = newm[r];
        }
        #pragma unroll
        for (int ni = 0; ni < 8; ++ni)
            #pragma unroll
            for (int u = 0; u < 4; ++u) {
                float p = expf(accS[ni][u] - newm[u >> 1]);
                accS[ni][u] = p;
                psum[u >> 1] += p;
            }
        #pragma unroll
        for (int r = 0; r < 2; ++r) {
            psum[r] += __shfl_xor_sync(0xffffffffu, psum[r], 1);
            psum[r] += __shfl_xor_sync(0xffffffffu, psum[r], 2);
            lrow[r] = lrow[r] * alpha[r] + psum[r];
        }
        #pragma unroll
        for (int ni = 0; ni < 8; ++ni)
            #pragma unroll
            for (int u = 0; u < 4; ++u)
                accO[ni][u] *= alpha[u >> 1];

        // ---- O += P V (3-term split), P frags built in registers ----
        #pragma unroll
        for (int j = 0; j < 4; ++j) {
            uint32_t afh[4], afl[4];
            split2(accS[2 * j][0],     accS[2 * j][1],     afh[0], afl[0]);
            split2(accS[2 * j][2],     accS[2 * j][3],     afh[1], afl[1]);
            split2(accS[2 * j + 1][0], accS[2 * j + 1][1], afh[2], afl[2]);
            split2(accS[2 * j + 1][2], accS[2 * j + 1][3], afh[3], afl[3]);
            #pragma unroll
            for (int g = 0; g < 4; ++g) {
                uint32_t vh[4], vl[4];
                uint32_t off = (uint32_t)((j * 16 + (lane & 15)) * FST + g * 16 + ((lane >> 4) << 3)) * 2;
                ldsm4t(vh, sVh_b + off);
                ldsm4t(vl, sVl_b + off);
                mma16816(accO[2 * g],     afh, vh);
                mma16816(accO[2 * g],     afh, vl);
                mma16816(accO[2 * g],     afl, vh);
                mma16816(accO[2 * g + 1], afh, vh + 2);
                mma16816(accO[2 * g + 1], afh, vl + 2);
                mma16816(accO[2 * g + 1], afl, vh + 2);
            }
        }
        __syncthreads();
    }

    // ---- write ctx ----
    #pragma unroll
    for (int r = 0; r < 2; ++r) {
        float inv = 1.f / lrow[r];
        #pragma unroll
        for (int ni = 0; ni < 8; ++ni) {
            float2 o = {accO[ni][2 * r] * inv, accO[ni][2 * r + 1] * inv};
            *(float2*)(ctx + (size_t)(b * LL + qr0 + 8 * r) * DD + h * DKH + ni * 8 + ec) = o;
        }
    }
}

// ------------- LayerNorm over last dim (768) ----------------------------------
__global__ void __launch_bounds__(256)
ln_kernel(const float* __restrict__ X, const float* __restrict__ g,
          const float* __restrict__ bt, float* __restrict__ O)
{
    const int row = blockIdx.x;
    const float* x = X + (size_t)row * DD;
    const int tid = threadIdx.x;

    float v[3];
    #pragma unroll
    for (int i = 0; i < 3; ++i) v[i] = x[tid + i * 256];

    __shared__ float red[256];
    float s = v[0] + v[1] + v[2];
    red[tid] = s; __syncthreads();
    for (int st = 128; st > 0; st >>= 1) {
        if (tid < st) red[tid] += red[tid + st];
        __syncthreads();
    }
    float mean = red[0] * (1.0f / DD);
    __syncthreads();

    float d0 = v[0] - mean, d1 = v[1] - mean, d2 = v[2] - mean;
    red[tid] = d0 * d0 + d1 * d1 + d2 * d2; __syncthreads();
    for (int st = 128; st > 0; st >>= 1) {
        if (tid < st) red[tid] += red[tid + st];
        __syncthreads();
    }
    float var = red[0] * (1.0f / DD);
    float inv = rsqrtf(var + 1e-5f);

    float* o = O + (size_t)row * DD;
    #pragma unroll
    for (int i = 0; i < 3; ++i) {
        int c = tid + i * 256;
        o[c] = (v[i] - mean) * inv * g[c] + bt[c];
    }
}

// ------------------------------- launch ---------------------------------------
extern "C" void kernel_launch(void* const* d_in, const int* in_sizes, int n_in,
                              void* d_out, int out_size)
{
    const float* tokens = (const float*)d_in[0];
    const float* pos    = (const float*)d_in[1];
    const float* pmask  = (const float*)d_in[2];
    const float* amask  = (const float*)d_in[3];
    const unsigned char* pad = (const unsigned char*)d_in[4];
    const float* Wq = (const float*)d_in[5];
    const float* bq = (const float*)d_in[6];
    const float* Wk = (const float*)d_in[7];
    const float* bk = (const float*)d_in[8];
    const float* Wv = (const float*)d_in[9];
    const float* bv = (const float*)d_in[10];
    const float* Wo = (const float*)d_in[11];
    const float* bo = (const float*)d_in[12];
    const float* table = (const float*)d_in[13];
    const float* W1 = (const float*)d_in[14];
    const float* b1 = (const float*)d_in[15];
    const float* W2 = (const float*)d_in[16];
    const float* b2 = (const float*)d_in[17];
    const float* ln1g = (const float*)d_in[18];
    const float* ln1b = (const float*)d_in[19];
    const float* ln2g = (const float*)d_in[20];
    const float* ln2b = (const float*)d_in[21];
    float* out = (float*)d_out;

    float *Cb, *Pb, *Tb, *Fb;
    cudaGetSymbolAddress((void**)&Cb, g_ctx);
    cudaGetSymbolAddress((void**)&Pb, g_pre);
    cudaGetSymbolAddress((void**)&Tb, g_t1);
    cudaGetSymbolAddress((void**)&Fb, g_ff);

    __nv_bfloat16 *qh, *ql, *kh, *kl, *vh, *vl;
    cudaGetSymbolAddress((void**)&qh, g_qh); cudaGetSymbolAddress((void**)&ql, g_ql);
    cudaGetSymbolAddress((void**)&kh, g_kh); cudaGetSymbolAddress((void**)&kl, g_kl);
    cudaGetSymbolAddress((void**)&vh, g_vh); cudaGetSymbolAddress((void**)&vl, g_vl);

    __nv_bfloat16 *wqh, *wql, *wkh, *wkl, *wvh, *wvl, *woh, *wol, *w1h, *w1l, *w2h, *w2l;
    cudaGetSymbolAddress((void**)&wqh, g_wqh); cudaGetSymbolAddress((void**)&wql, g_wql);
    cudaGetSymbolAddress((void**)&wkh, g_wkh); cudaGetSymbolAddress((void**)&wkl, g_wkl);
    cudaGetSymbolAddress((void**)&wvh, g_wvh); cudaGetSymbolAddress((void**)&wvl, g_wvl);
    cudaGetSymbolAddress((void**)&woh, g_woh); cudaGetSymbolAddress((void**)&wol, g_wol);
    cudaGetSymbolAddress((void**)&w1h, g_w1h); cudaGetSymbolAddress((void**)&w1l, g_w1l);
    cudaGetSymbolAddress((void**)&w2h, g_w2h); cudaGetSymbolAddress((void**)&w2l, g_w2l);

    // weight transpose + split
    dim3 gw(DD / 32, DD / 32);
    cvt_wT<<<gw, 256>>>(Wq, wqh, wql, DD, DD);
    cvt_wT<<<gw, 256>>>(Wk, wkh, wkl, DD, DD);
    cvt_wT<<<gw, 256>>>(Wv, wvh, wvl, DD, DD);
    cvt_wT<<<gw, 256>>>(Wo, woh, wol, DD, DD);
    cvt_wT<<<dim3(FF / 32, DD / 32), 256>>>(W1, w1h, w1l, DD, FF);
    cvt_wT<<<dim3(DD / 32, FF / 32), 256>>>(W2, w2h, w2l, FF, DD);

    dim3 gD(DD / 128, BL / 128);
    dim3 gF(FF / 128, BL / 128);

    // QKV -> bf16 hi/lo directly
    gemm_mma<3><<<gD, 256>>>(tokens, wqh, wql, bq, nullptr, nullptr, qh, ql, DD, DD);
    gemm_mma<3><<<gD, 256>>>(tokens, wkh, wkl, bk, nullptr, nullptr, kh, kl, DD, DD);
    gemm_mma<3><<<gD, 256>>>(tokens, wvh, wvl, bv, nullptr, nullptr, vh, vl, DD, DD);

    // fused attention
    dim3 gfa(LL / 64, BB * HH);
    flash_kernel<<<gfa, 128>>>(qh, ql, kh, kl, vh, vl, pos, pmask, amask, pad, table, Cb);

    // out proj + residual, LN1
    gemm_mma<2><<<gD, 256>>>(Cb, woh, wol, bo, tokens, Pb, nullptr, nullptr, DD, DD);
    ln_kernel<<<BL, 256>>>(Pb, ln1g, ln1b, Tb);

    // FFN
    gemm_mma<1><<<gF, 256>>>(Tb, w1h, w1l, b1, nullptr, Fb, nullptr, nullptr, DD, FF);
    gemm_mma<2><<<gD, 256>>>(Fb, w2h, w2l, b2, Tb, Pb, nullptr, nullptr, FF, DD);
    ln_kernel<<<BL, 256>>>(Pb, ln2g, ln2b, out);
}